// round 7
// baseline (speedup 1.0000x reference)
#include <cuda_runtime.h>
#include <math.h>

#define B_SZ 256
#define N_SZ 512
#define D_SZ 256
#define R_SZ 64
#define NT   8          // n-tiles per batch
#define TN   64         // rows per n-tile

// Scratch (allocation-free: __device__ globals)
__device__ float g_M[D_SZ * D_SZ];          // M = Wq^T @ Wk
__device__ float g_p[B_SZ * D_SZ];          // p = tok @ M
__device__ float g_s[B_SZ * N_SZ];          // masked+scaled scores
__device__ float g_mt[B_SZ * NT];           // tile max
__device__ float g_zt[B_SZ * NT];           // tile sum of exp
__device__ float g_part[B_SZ * NT * D_SZ];  // unnormalized partial g

// ---------------------------------------------------------------------------
// kM: M[d,j] = sum_r Wq[r,d] * Wk[r,j]    (32x32 tiles, K=64)
// ---------------------------------------------------------------------------
__global__ void __launch_bounds__(256) kM_wqwk(
    const float* __restrict__ Wq, const float* __restrict__ Wk)
{
    __shared__ float A[32][33];
    __shared__ float Bs[32][33];
    const int d0 = blockIdx.y * 32, j0 = blockIdx.x * 32;
    const int tid = threadIdx.x, tx = tid & 31, ty = tid >> 5;
    float acc[4] = {0.f, 0.f, 0.f, 0.f};

    for (int k0 = 0; k0 < R_SZ; k0 += 32) {
        #pragma unroll
        for (int r = 0; r < 4; r++) {
            const int kk = ty + 8 * r;
            A[kk][tx]  = Wq[(k0 + kk) * D_SZ + d0 + tx];
            Bs[kk][tx] = Wk[(k0 + kk) * D_SZ + j0 + tx];
        }
        __syncthreads();
        #pragma unroll
        for (int kk = 0; kk < 32; kk++) {
            const float bv = Bs[kk][tx];
            #pragma unroll
            for (int r = 0; r < 4; r++)
                acc[r] += A[kk][ty + 8 * r] * bv;
        }
        __syncthreads();
    }
    #pragma unroll
    for (int r = 0; r < 4; r++)
        g_M[(d0 + ty + 8 * r) * D_SZ + j0 + tx] = acc[r];
}

// ---------------------------------------------------------------------------
// k1: p[b,j] = sum_d tok[b,d] * M[d,j]
// ---------------------------------------------------------------------------
__global__ void __launch_bounds__(256) k1_p(const float* __restrict__ tok)
{
    __shared__ float As[32][33];
    __shared__ float Bs[32][33];
    const int j0 = blockIdx.x * 32, b0 = blockIdx.y * 32;
    const int tid = threadIdx.x, tx = tid & 31, ty = tid >> 5;
    float acc[4] = {0.f, 0.f, 0.f, 0.f};

    for (int d0 = 0; d0 < D_SZ; d0 += 32) {
        #pragma unroll
        for (int r = 0; r < 4; r++) {
            const int row = ty + 8 * r;
            As[row][tx] = tok[(b0 + row) * D_SZ + d0 + tx];
            Bs[row][tx] = g_M[(d0 + row) * D_SZ + j0 + tx];
        }
        __syncthreads();
        #pragma unroll
        for (int kk = 0; kk < 32; kk++) {
            const float bv = Bs[kk][tx];
            #pragma unroll
            for (int r = 0; r < 4; r++)
                acc[r] += As[ty + 8 * r][kk] * bv;
        }
        __syncthreads();
    }
    #pragma unroll
    for (int r = 0; r < 4; r++)
        g_p[(b0 + ty + 8 * r) * D_SZ + j0 + tx] = acc[r];
}

// ---------------------------------------------------------------------------
// K2a: single logical H pass per tile, NO smem staging.
// Phase 1: scores from GMEM (fills L2/L1). Phase 2: partial-g re-reads the
// same 64 KB tile -> L2/L1 hits. Tiny smem => 5-6 CTAs/SM for latency hiding.
// ---------------------------------------------------------------------------
__global__ void __launch_bounds__(256) k2a_pass(
    const float* __restrict__ H,
    const int* __restrict__ mask,
    const float* __restrict__ log_scale)
{
    __shared__ __align__(16) float p_s[D_SZ];
    __shared__ float s_s[TN];
    __shared__ float w_s[TN];

    const int b = blockIdx.y;
    const int t = blockIdx.x;
    const int n0 = t * TN;
    const int tid = threadIdx.x;
    const int w = tid >> 5, l = tid & 31;

    p_s[tid] = g_p[b * D_SZ + tid];
    const float inv_scale = 1.f / fmaxf(__expf(log_scale[0]), 0.1f);
    __syncthreads();

    const float* Hb = H + (size_t)b * N_SZ * D_SZ + (size_t)n0 * D_SZ;
    const float4* p4 = reinterpret_cast<const float4*>(p_s);
    const float4 pf0 = p4[l];
    const float4 pf1 = p4[l + 32];

    // Phase 1: warp w computes rows n = w + 8*i, unrolled 2 for MLP
    #pragma unroll
    for (int i = 0; i < 8; i += 2) {
        const int na = w + 8 * i;
        const int nb = na + 8;
        const float4* h4a = reinterpret_cast<const float4*>(Hb + na * D_SZ);
        const float4* h4b = reinterpret_cast<const float4*>(Hb + nb * D_SZ);
        float4 a0 = h4a[l], a1 = h4a[l + 32];
        float4 b0 = h4b[l], b1 = h4b[l + 32];

        float pa = a0.x * pf0.x + a0.y * pf0.y + a0.z * pf0.z + a0.w * pf0.w
                 + a1.x * pf1.x + a1.y * pf1.y + a1.z * pf1.z + a1.w * pf1.w;
        float pb = b0.x * pf0.x + b0.y * pf0.y + b0.z * pf0.z + b0.w * pf0.w
                 + b1.x * pf1.x + b1.y * pf1.y + b1.z * pf1.z + b1.w * pf1.w;

        #pragma unroll
        for (int off = 16; off > 0; off >>= 1) {
            pa += __shfl_xor_sync(0xffffffffu, pa, off);
            pb += __shfl_xor_sync(0xffffffffu, pb, off);
        }
        if (l == 0) {
            float sa = (mask[b * N_SZ + n0 + na] != 0) ? pa * inv_scale : -INFINITY;
            float sb = (mask[b * N_SZ + n0 + nb] != 0) ? pb * inv_scale : -INFINITY;
            s_s[na] = sa;  g_s[b * N_SZ + n0 + na] = sa;
            s_s[nb] = sb;  g_s[b * N_SZ + n0 + nb] = sb;
        }
    }
    __syncthreads();

    // Tile-local softmax stats (warp 0)
    if (w == 0) {
        float v0 = s_s[l], v1 = s_s[l + 32];
        float v = fmaxf(v0, v1);
        #pragma unroll
        for (int off = 16; off > 0; off >>= 1)
            v = fmaxf(v, __shfl_xor_sync(0xffffffffu, v, off));
        const float m_t = v;
        const float mu = (m_t == -INFINITY) ? 0.f : m_t;   // NaN guard
        const float w0 = __expf(v0 - mu);
        const float w1 = __expf(v1 - mu);
        w_s[l] = w0;
        w_s[l + 32] = w1;
        float z = w0 + w1;
        #pragma unroll
        for (int off = 16; off > 0; off >>= 1)
            z += __shfl_xor_sync(0xffffffffu, z, off);
        if (l == 0) {
            g_mt[b * NT + t] = m_t;
            g_zt[b * NT + t] = z;
        }
    }
    __syncthreads();

    // Phase 2: partial g; re-read tile (L2/L1 hits), 4 independent accs
    float a0 = 0.f, a1 = 0.f, a2 = 0.f, a3 = 0.f;
    #pragma unroll 4
    for (int n = 0; n < TN; n += 4) {
        a0 += w_s[n]     * Hb[(n)     * D_SZ + tid];
        a1 += w_s[n + 1] * Hb[(n + 1) * D_SZ + tid];
        a2 += w_s[n + 2] * Hb[(n + 2) * D_SZ + tid];
        a3 += w_s[n + 3] * Hb[(n + 3) * D_SZ + tid];
    }
    g_part[(b * NT + t) * D_SZ + tid] = (a0 + a1) + (a2 + a3);
}

// ---------------------------------------------------------------------------
// K3 fused: per (e-tile, b-tile): combine stats -> g-tile in smem -> ctx GEMM.
// The ex==0 CTA column also writes exact alpha for its 32 b-rows.
// ---------------------------------------------------------------------------
__global__ void __launch_bounds__(256) k3_fused(
    const float* __restrict__ Wv,
    float* __restrict__ alpha_out,
    float* __restrict__ ctx)
{
    __shared__ float Gs[32][257];   // g tile [b-row][d]
    __shared__ float Ws[32][33];    // Wv chunk [e-row][d-chunk]
    __shared__ float f_s[32][8];    // per-row tile factors e_t/Z
    __shared__ float M_s[32], iZ_s[32];

    const int e0 = blockIdx.x * 32, b0 = blockIdx.y * 32;
    const int tid = threadIdx.x, tx = tid & 31, ty = tid >> 5;

    // Step 1: per-b combine stats (32 threads)
    if (tid < 32) {
        const int b = b0 + tid;
        float mt[NT], M = -INFINITY;
        #pragma unroll
        for (int t = 0; t < NT; t++) {
            mt[t] = g_mt[b * NT + t];
            M = fmaxf(M, mt[t]);
        }
        float Z = 0.f, e[NT];
        #pragma unroll
        for (int t = 0; t < NT; t++) {
            e[t] = (mt[t] == -INFINITY) ? 0.f : __expf(mt[t] - M);
            Z += g_zt[b * NT + t] * e[t];
        }
        const float iZ = 1.f / Z;
        #pragma unroll
        for (int t = 0; t < NT; t++) f_s[tid][t] = e[t] * iZ;
        M_s[tid] = M;
        iZ_s[tid] = iZ;
    }
    __syncthreads();

    // Step 2: build g tile: Gs[row][tid] = sum_t f * g_part
    for (int row = 0; row < 32; row++) {
        float acc = 0.f;
        #pragma unroll
        for (int t = 0; t < NT; t++)
            acc += f_s[row][t] * g_part[((b0 + row) * NT + t) * D_SZ + tid];
        Gs[row][tid] = acc;
    }
    __syncthreads();

    // Step 3: ctx tile GEMM: ctx[b0+row][e0+col] = sum_d Gs[row][d]*Wv[col][d]
    float acc[4] = {0.f, 0.f, 0.f, 0.f};
    for (int d0 = 0; d0 < D_SZ; d0 += 32) {
        #pragma unroll
        for (int r = 0; r < 4; r++)
            Ws[ty + 8 * r][tx] = Wv[(e0 + ty + 8 * r) * D_SZ + d0 + tx];
        __syncthreads();
        #pragma unroll
        for (int kk = 0; kk < 32; kk++) {
            const float wv = Ws[tx][kk];
            #pragma unroll
            for (int r = 0; r < 4; r++)
                acc[r] += Gs[ty + 8 * r][d0 + kk] * wv;
        }
        __syncthreads();
    }
    #pragma unroll
    for (int r = 0; r < 4; r++)
        ctx[(b0 + ty + 8 * r) * D_SZ + e0 + tx] = acc[r];

    // Step 4: alpha for these 32 b-rows (only ex==0 CTAs)
    if (blockIdx.x == 0) {
        for (int i = tid; i < 32 * N_SZ; i += 256) {
            const int row = i >> 9;          // /512
            const int n = i & (N_SZ - 1);
            alpha_out[(b0 + row) * N_SZ + n] =
                __expf(g_s[(b0 + row) * N_SZ + n] - M_s[row]) * iZ_s[row];
        }
    }
}

// ---------------------------------------------------------------------------
extern "C" void kernel_launch(void* const* d_in, const int* in_sizes, int n_in,
                              void* d_out, int out_size) {
    const float* tok  = (const float*)d_in[0];
    const float* H    = (const float*)d_in[1];
    const int* mask   = (const int*)d_in[2];
    const float* Wq   = (const float*)d_in[3];
    const float* Wk   = (const float*)d_in[4];
    const float* Wv   = (const float*)d_in[5];
    const float* ls   = (const float*)d_in[6];

    float* out_alpha = (float*)d_out;                 // [256,512]
    float* out_ctx   = out_alpha + B_SZ * N_SZ;       // [256,256]

    kM_wqwk<<<dim3(8, 8), 256>>>(Wq, Wk);
    k1_p<<<dim3(8, 8), 256>>>(tok);
    k2a_pass<<<dim3(NT, B_SZ), 256>>>(H, mask, ls);
    k3_fused<<<dim3(8, 8), 256>>>(Wv, out_alpha, out_ctx);
}

// round 8
// speedup vs baseline: 1.4576x; 1.4576x over previous
#include <cuda_runtime.h>
#include <math.h>

#define B_SZ 256
#define N_SZ 512
#define D_SZ 256
#define R_SZ 64
#define NT   8          // n-tiles per batch
#define TN   64         // rows per n-tile

// Scratch (allocation-free: __device__ globals)
__device__ float g_M[D_SZ * D_SZ];          // M = Wq^T @ Wk
__device__ float g_p[B_SZ * D_SZ];          // p = tok @ M
__device__ float g_s[B_SZ * N_SZ];          // masked+scaled scores
__device__ float g_mt[B_SZ * NT];           // tile max
__device__ float g_zt[B_SZ * NT];           // tile sum of exp
__device__ float g_part[B_SZ * NT * D_SZ];  // unnormalized partial g
__device__ float g_g[B_SZ * D_SZ];          // final weighted sum

// ---------------------------------------------------------------------------
// kM: M[d,j] = sum_r Wq[r,d] * Wk[r,j]    (32x32 tiles, K=64)
// ---------------------------------------------------------------------------
__global__ void __launch_bounds__(256) kM_wqwk(
    const float* __restrict__ Wq, const float* __restrict__ Wk)
{
    __shared__ float A[32][33];
    __shared__ float Bs[32][33];
    const int d0 = blockIdx.y * 32, j0 = blockIdx.x * 32;
    const int tid = threadIdx.x, tx = tid & 31, ty = tid >> 5;
    float acc[4] = {0.f, 0.f, 0.f, 0.f};

    for (int k0 = 0; k0 < R_SZ; k0 += 32) {
        #pragma unroll
        for (int r = 0; r < 4; r++) {
            const int kk = ty + 8 * r;
            A[kk][tx]  = Wq[(k0 + kk) * D_SZ + d0 + tx];
            Bs[kk][tx] = Wk[(k0 + kk) * D_SZ + j0 + tx];
        }
        __syncthreads();
        #pragma unroll
        for (int kk = 0; kk < 32; kk++) {
            const float bv = Bs[kk][tx];
            #pragma unroll
            for (int r = 0; r < 4; r++)
                acc[r] += A[kk][ty + 8 * r] * bv;
        }
        __syncthreads();
    }
    #pragma unroll
    for (int r = 0; r < 4; r++)
        g_M[(d0 + ty + 8 * r) * D_SZ + j0 + tx] = acc[r];
}

// ---------------------------------------------------------------------------
// k1: p[b,j] = sum_d tok[b,d] * M[d,j]
// ---------------------------------------------------------------------------
__global__ void __launch_bounds__(256) k1_p(const float* __restrict__ tok)
{
    __shared__ float As[32][33];
    __shared__ float Bs[32][33];
    const int j0 = blockIdx.x * 32, b0 = blockIdx.y * 32;
    const int tid = threadIdx.x, tx = tid & 31, ty = tid >> 5;
    float acc[4] = {0.f, 0.f, 0.f, 0.f};

    for (int d0 = 0; d0 < D_SZ; d0 += 32) {
        #pragma unroll
        for (int r = 0; r < 4; r++) {
            const int row = ty + 8 * r;
            As[row][tx] = tok[(b0 + row) * D_SZ + d0 + tx];
            Bs[row][tx] = g_M[(d0 + row) * D_SZ + j0 + tx];
        }
        __syncthreads();
        #pragma unroll
        for (int kk = 0; kk < 32; kk++) {
            const float bv = Bs[kk][tx];
            #pragma unroll
            for (int r = 0; r < 4; r++)
                acc[r] += As[ty + 8 * r][kk] * bv;
        }
        __syncthreads();
    }
    #pragma unroll
    for (int r = 0; r < 4; r++)
        g_p[(b0 + ty + 8 * r) * D_SZ + j0 + tx] = acc[r];
}

// ---------------------------------------------------------------------------
// K2a: single logical H pass per tile, NO smem staging (R6 version: ~35us).
// Phase 1: scores from GMEM (fills L1/L2). Phase 2: partial-g re-reads the
// same 64 KB tile -> cache hits. Tiny smem => high occupancy.
// ---------------------------------------------------------------------------
__global__ void __launch_bounds__(256) k2a_pass(
    const float* __restrict__ H,
    const int* __restrict__ mask,
    const float* __restrict__ log_scale)
{
    __shared__ __align__(16) float p_s[D_SZ];
    __shared__ float s_s[TN];
    __shared__ float w_s[TN];

    const int b = blockIdx.y;
    const int t = blockIdx.x;
    const int n0 = t * TN;
    const int tid = threadIdx.x;
    const int w = tid >> 5, l = tid & 31;

    p_s[tid] = g_p[b * D_SZ + tid];
    const float inv_scale = 1.f / fmaxf(__expf(log_scale[0]), 0.1f);
    __syncthreads();

    const float* Hb = H + (size_t)b * N_SZ * D_SZ + (size_t)n0 * D_SZ;
    const float4* p4 = reinterpret_cast<const float4*>(p_s);
    const float4 pf0 = p4[l];
    const float4 pf1 = p4[l + 32];

    // Phase 1: warp w computes rows n = w + 8*i, unrolled 2 for MLP
    #pragma unroll
    for (int i = 0; i < 8; i += 2) {
        const int na = w + 8 * i;
        const int nb = na + 8;
        const float4* h4a = reinterpret_cast<const float4*>(Hb + na * D_SZ);
        const float4* h4b = reinterpret_cast<const float4*>(Hb + nb * D_SZ);
        float4 a0 = h4a[l], a1 = h4a[l + 32];
        float4 b0 = h4b[l], b1 = h4b[l + 32];

        float pa = a0.x * pf0.x + a0.y * pf0.y + a0.z * pf0.z + a0.w * pf0.w
                 + a1.x * pf1.x + a1.y * pf1.y + a1.z * pf1.z + a1.w * pf1.w;
        float pb = b0.x * pf0.x + b0.y * pf0.y + b0.z * pf0.z + b0.w * pf0.w
                 + b1.x * pf1.x + b1.y * pf1.y + b1.z * pf1.z + b1.w * pf1.w;

        #pragma unroll
        for (int off = 16; off > 0; off >>= 1) {
            pa += __shfl_xor_sync(0xffffffffu, pa, off);
            pb += __shfl_xor_sync(0xffffffffu, pb, off);
        }
        if (l == 0) {
            float sa = (mask[b * N_SZ + n0 + na] != 0) ? pa * inv_scale : -INFINITY;
            float sb = (mask[b * N_SZ + n0 + nb] != 0) ? pb * inv_scale : -INFINITY;
            s_s[na] = sa;  g_s[b * N_SZ + n0 + na] = sa;
            s_s[nb] = sb;  g_s[b * N_SZ + n0 + nb] = sb;
        }
    }
    __syncthreads();

    // Tile-local softmax stats (warp 0)
    if (w == 0) {
        float v0 = s_s[l], v1 = s_s[l + 32];
        float v = fmaxf(v0, v1);
        #pragma unroll
        for (int off = 16; off > 0; off >>= 1)
            v = fmaxf(v, __shfl_xor_sync(0xffffffffu, v, off));
        const float m_t = v;
        const float mu = (m_t == -INFINITY) ? 0.f : m_t;   // NaN guard
        const float w0 = __expf(v0 - mu);
        const float w1 = __expf(v1 - mu);
        w_s[l] = w0;
        w_s[l + 32] = w1;
        float z = w0 + w1;
        #pragma unroll
        for (int off = 16; off > 0; off >>= 1)
            z += __shfl_xor_sync(0xffffffffu, z, off);
        if (l == 0) {
            g_mt[b * NT + t] = m_t;
            g_zt[b * NT + t] = z;
        }
    }
    __syncthreads();

    // Phase 2: partial g; re-read tile (cache hits), 4 independent accs
    float a0 = 0.f, a1 = 0.f, a2 = 0.f, a3 = 0.f;
    #pragma unroll 4
    for (int n = 0; n < TN; n += 4) {
        a0 += w_s[n]     * Hb[(n)     * D_SZ + tid];
        a1 += w_s[n + 1] * Hb[(n + 1) * D_SZ + tid];
        a2 += w_s[n + 2] * Hb[(n + 2) * D_SZ + tid];
        a3 += w_s[n + 3] * Hb[(n + 3) * D_SZ + tid];
    }
    g_part[(b * NT + t) * D_SZ + tid] = (a0 + a1) + (a2 + a3);
}

// ---------------------------------------------------------------------------
// K2b: combine tile stats -> exact alpha + final g.  grid 256 (b), block 256
// ---------------------------------------------------------------------------
__global__ void __launch_bounds__(256) k2b_combine(
    float* __restrict__ alpha_out)
{
    __shared__ float f_s[NT];
    __shared__ float sm_M, sm_invZ;
    const int b = blockIdx.x;
    const int tid = threadIdx.x;

    if (tid < 32) {
        const float m_t = (tid < NT) ? g_mt[b * NT + tid] : -INFINITY;
        const float z_t = (tid < NT) ? g_zt[b * NT + tid] : 0.f;
        float M = m_t;
        #pragma unroll
        for (int off = 16; off > 0; off >>= 1)
            M = fmaxf(M, __shfl_xor_sync(0xffffffffu, M, off));
        const float e = (m_t == -INFINITY) ? 0.f : __expf(m_t - M);
        float Z = z_t * e;
        #pragma unroll
        for (int off = 16; off > 0; off >>= 1)
            Z += __shfl_xor_sync(0xffffffffu, Z, off);
        const float invZ = 1.f / Z;
        if (tid < NT) f_s[tid] = e * invZ;
        if (tid == 0) { sm_M = M; sm_invZ = invZ; }
    }
    __syncthreads();

    const float M = sm_M, invZ = sm_invZ;

    // exact alpha from stored scores (exp(-inf - M) = 0 for masked)
    alpha_out[b * N_SZ + tid] = __expf(g_s[b * N_SZ + tid] - M) * invZ;
    alpha_out[b * N_SZ + tid + 256] =
        __expf(g_s[b * N_SZ + tid + 256] - M) * invZ;

    // g[b,d] = sum_t f_t * g_part[b,t,d]
    float acc = 0.f;
    #pragma unroll
    for (int t = 0; t < NT; t++)
        acc += f_s[t] * g_part[(b * NT + t) * D_SZ + tid];
    g_g[b * D_SZ + tid] = acc;
}

// ---------------------------------------------------------------------------
// K3: ctx[b,e] = sum_d g[b,d] * Wv[e,d]   (32x32 tiled NT GEMM)
// ---------------------------------------------------------------------------
__global__ void __launch_bounds__(256) k3_ctx(
    const float* __restrict__ Wv, float* __restrict__ ctx)
{
    __shared__ float Gs[32][33];
    __shared__ float Ws[32][33];
    const int e0 = blockIdx.x * 32, b0 = blockIdx.y * 32;
    const int tid = threadIdx.x, tx = tid & 31, ty = tid >> 5;
    float acc[4] = {0.f, 0.f, 0.f, 0.f};

    for (int d0 = 0; d0 < D_SZ; d0 += 32) {
        #pragma unroll
        for (int r = 0; r < 4; r++) {
            const int row = ty + 8 * r;
            Gs[row][tx] = g_g[(b0 + row) * D_SZ + d0 + tx];
            Ws[row][tx] = Wv[(e0 + row) * D_SZ + d0 + tx];
        }
        __syncthreads();
        #pragma unroll
        for (int kk = 0; kk < 32; kk++) {
            const float wv = Ws[tx][kk];
            #pragma unroll
            for (int r = 0; r < 4; r++)
                acc[r] += Gs[ty + 8 * r][kk] * wv;
        }
        __syncthreads();
    }
    #pragma unroll
    for (int r = 0; r < 4; r++)
        ctx[(b0 + ty + 8 * r) * D_SZ + e0 + tx] = acc[r];
}

// ---------------------------------------------------------------------------
extern "C" void kernel_launch(void* const* d_in, const int* in_sizes, int n_in,
                              void* d_out, int out_size) {
    const float* tok  = (const float*)d_in[0];
    const float* H    = (const float*)d_in[1];
    const int* mask   = (const int*)d_in[2];
    const float* Wq   = (const float*)d_in[3];
    const float* Wk   = (const float*)d_in[4];
    const float* Wv   = (const float*)d_in[5];
    const float* ls   = (const float*)d_in[6];

    float* out_alpha = (float*)d_out;                 // [256,512]
    float* out_ctx   = out_alpha + B_SZ * N_SZ;       // [256,256]

    kM_wqwk<<<dim3(8, 8), 256>>>(Wq, Wk);
    k1_p<<<dim3(8, 8), 256>>>(tok);
    k2a_pass<<<dim3(NT, B_SZ), 256>>>(H, mask, ls);
    k2b_combine<<<B_SZ, 256>>>(out_alpha);
    k3_ctx<<<dim3(8, 8), 256>>>(Wv, out_ctx);
}